// round 3
// baseline (speedup 1.0000x reference)
#include <cuda_runtime.h>
#include <cuda_bf16.h>
#include <cstdint>

// ---------------- problem constants ----------------
#define B_      4
#define CIN     256
#define COUT    128
#define HLO     64
#define WLO     64
#define PLO     (HLO*WLO)      // 4096 low-res pixels
#define CRED    32
#define GROUPS  8
#define GC_     16
#define KK      25             // 5x5
#define SPAN    (KK*GROUPS)    // 200
#define HF      128            // full res
#define WF      128

// ---------------- scratch (device globals; no allocs allowed) ----------------
__device__ float g_h0 [B_ * COUT * PLO];   // 8.4 MB : conv1x1 output at 64x64
__device__ float g_wgt[B_ * SPAN * PLO];   // 13.1 MB: involution weights at 64x64

// ---------------- helpers: packed f32x2 ----------------
__device__ __forceinline__ unsigned long long fma2(unsigned long long a,
                                                   unsigned long long b,
                                                   unsigned long long c) {
    unsigned long long d;
    asm("fma.rn.f32x2 %0, %1, %2, %3;" : "=l"(d) : "l"(a), "l"(b), "l"(c));
    return d;
}
__device__ __forceinline__ unsigned long long pack2(float v) {
    unsigned long long d;
    asm("mov.b64 %0, {%1, %1};" : "=l"(d) : "f"(v), "f"(v));
    return d;
}
union F2U { unsigned long long u; float2 f; };

// =====================================================================
// K1: h0[b,co,p] = sum_ci w1x1[co,ci] * x[b,ci,p] + b1x1[co]
// GEMM per batch: [128 x 256] x [256 x 4096]. Block tile 128(co) x 128(px).
// =====================================================================
__global__ __launch_bounds__(256, 1)
void k1_conv1x1(const float* __restrict__ x,
                const float* __restrict__ w,
                const float* __restrict__ bias) {
    __shared__ float Xs[8][128];
    __shared__ float Ws[8][132];

    const int bb = blockIdx.y;
    const int p0 = blockIdx.x * 128;
    const int t  = threadIdx.x;
    const int ty = t >> 4;     // 0..15
    const int tx = t & 15;     // 0..15

    unsigned long long acc[8][4];
#pragma unroll
    for (int i = 0; i < 8; i++)
#pragma unroll
        for (int j = 0; j < 4; j++) acc[i][j] = 0ull;

    const float* xb = x + (size_t)bb * CIN * PLO + p0;

    for (int k0 = 0; k0 < CIN; k0 += 8) {
        // load X tile: 8 k-rows x 128 pixels (one float4 per thread)
        {
            int kk = t >> 5;           // 0..7
            int c4 = (t & 31) * 4;     // 0..124
            float4 v = *(const float4*)(xb + (size_t)(k0 + kk) * PLO + c4);
            *(float4*)&Xs[kk][c4] = v;
        }
        // load W tile: transpose [co][k] -> Ws[kk][co]
        {
            int co  = t >> 1;
            int kk4 = (t & 1) * 4;
            float4 v = *(const float4*)(w + co * CIN + k0 + kk4);
            Ws[kk4 + 0][co] = v.x; Ws[kk4 + 1][co] = v.y;
            Ws[kk4 + 2][co] = v.z; Ws[kk4 + 3][co] = v.w;
        }
        __syncthreads();
#pragma unroll
        for (int kk = 0; kk < 8; kk++) {
            unsigned long long wp[8];
#pragma unroll
            for (int i = 0; i < 8; i++) wp[i] = pack2(Ws[kk][ty + 16 * i]);
            unsigned long long xr[4];
#pragma unroll
            for (int j = 0; j < 4; j++)
                xr[j] = *(const unsigned long long*)&Xs[kk][2 * tx + 32 * j];
#pragma unroll
            for (int i = 0; i < 8; i++)
#pragma unroll
                for (int j = 0; j < 4; j++)
                    acc[i][j] = fma2(wp[i], xr[j], acc[i][j]);
        }
        __syncthreads();
    }

#pragma unroll
    for (int i = 0; i < 8; i++) {
        int co = ty + 16 * i;
        float bv = bias[co];
        float* op = g_h0 + ((size_t)bb * COUT + co) * PLO + p0;
#pragma unroll
        for (int j = 0; j < 4; j++) {
            F2U v; v.u = acc[i][j];
            float2 o = make_float2(v.f.x + bv, v.f.y + bv);
            *(float2*)&op[2 * tx + 32 * j] = o;
        }
    }
}

// =====================================================================
// K2: kernel-generation branch at 64x64 (exploits nearest-upsample):
//   r   = relu(BN(w_red @ h0 + b_red))       [32  x tile]
//   wgt = w_span @ r + b_span                [200 x tile]
// Block: 128-pixel tile, 256 threads.
// =====================================================================
__global__ __launch_bounds__(256, 1)
void k2_kernelgen(const float* __restrict__ w_red,  const float* __restrict__ b_red,
                  const float* __restrict__ gamma,  const float* __restrict__ beta,
                  const float* __restrict__ mean,   const float* __restrict__ var,
                  const float* __restrict__ w_span, const float* __restrict__ b_span) {
    __shared__ float Hs[32][128];
    __shared__ float Wrs[32][33];
    __shared__ float Rs[32][132];

    const int bb = blockIdx.y;
    const int p0 = blockIdx.x * 128;
    const int t  = threadIdx.x;
    const int ty = t >> 4;   // 0..15
    const int tx = t & 15;   // 0..15

    // ---- stage A: r = relu(BN(conv_red(h0))) ----
    unsigned long long acc[2][4];
#pragma unroll
    for (int i = 0; i < 2; i++)
#pragma unroll
        for (int j = 0; j < 4; j++) acc[i][j] = 0ull;

    for (int k0 = 0; k0 < COUT; k0 += 32) {
        // H tile: 32 k-rows x 128 px (4 float4 per thread)
#pragma unroll
        for (int q = 0; q < 4; q++) {
            int f   = t + 256 * q;
            int row = f >> 5;
            int c4  = (f & 31) * 4;
            float4 v = *(const float4*)(g_h0 + ((size_t)(bb * COUT + k0 + row)) * PLO + p0 + c4);
            *(float4*)&Hs[row][c4] = v;
        }
        // W_red tile: transpose [cr][k] -> Wrs[kk][cr]
        {
            int cr  = t >> 3;          // 0..31
            int kk4 = (t & 7) * 4;     // 0..28
            float4 v = *(const float4*)(w_red + cr * COUT + k0 + kk4);
            Wrs[kk4 + 0][cr] = v.x; Wrs[kk4 + 1][cr] = v.y;
            Wrs[kk4 + 2][cr] = v.z; Wrs[kk4 + 3][cr] = v.w;
        }
        __syncthreads();
#pragma unroll
        for (int kk = 0; kk < 32; kk++) {
            unsigned long long wp0 = pack2(Wrs[kk][ty]);
            unsigned long long wp1 = pack2(Wrs[kk][ty + 16]);
#pragma unroll
            for (int j = 0; j < 4; j++) {
                unsigned long long xv = *(const unsigned long long*)&Hs[kk][2 * tx + 32 * j];
                acc[0][j] = fma2(wp0, xv, acc[0][j]);
                acc[1][j] = fma2(wp1, xv, acc[1][j]);
            }
        }
        __syncthreads();
    }

    // BN + ReLU -> Rs
#pragma unroll
    for (int i = 0; i < 2; i++) {
        int cr = ty + 16 * i;
        float sc  = gamma[cr] * rsqrtf(var[cr] + 1e-5f);
        float off = (b_red[cr] - mean[cr]) * sc + beta[cr];
#pragma unroll
        for (int j = 0; j < 4; j++) {
            F2U v; v.u = acc[i][j];
            float r0 = fmaxf(v.f.x * sc + off, 0.f);
            float r1 = fmaxf(v.f.y * sc + off, 0.f);
            Rs[cr][2 * tx + 32 * j]     = r0;
            Rs[cr][2 * tx + 32 * j + 1] = r1;
        }
    }
    __syncthreads();

    // ---- stage B: wgt = w_span @ r + b_span; thread t owns cout=t (t<200) ----
    if (t < SPAN) {
        const int co = t;
        unsigned long long wp[32];
        const float* wsp = w_span + co * CRED;
#pragma unroll
        for (int k = 0; k < 32; k++) wp[k] = pack2(__ldg(wsp + k));
        const float bs = b_span[co];
        float* wout = g_wgt + ((size_t)bb * SPAN + co) * PLO + p0;

        for (int p4 = 0; p4 < 128; p4 += 4) {
            unsigned long long a0 = pack2(bs), a1 = pack2(bs);
#pragma unroll
            for (int k = 0; k < 32; k++) {
                ulonglong2 rv = *(const ulonglong2*)&Rs[k][p4];
                a0 = fma2(wp[k], rv.x, a0);
                a1 = fma2(wp[k], rv.y, a1);
            }
            F2U u0, u1; u0.u = a0; u1.u = a1;
            float4 o = make_float4(u0.f.x, u0.f.y, u1.f.x, u1.f.y);
            *(float4*)&wout[p4] = o;
        }
    }
}

// =====================================================================
// K3: involution at full res, exploiting nearest-upsample:
//  out[b, g*16+c, 2m+py, 2n+px] = sum_{kh,kw} wgt0[b,g,kh*5+kw,m,n]
//                               * h0[b, g*16+c, m+(py+kh-2)>>1, n+(px+kw-2)>>1]
//  (zero outside low-res bounds == reference zero padding, exactly)
// Block: (16x16 low tile, group g, batch b); 256 threads = 16c x 16col.
// =====================================================================
__global__ __launch_bounds__(256, 2)
void k3_involution(float* __restrict__ outp) {
    __shared__ float Hs[16 * 336];        // 16 ch x (18x18 halo), c-stride 336
    __shared__ float Wg[KK * 256];        // [k][ml*16+nl]

    const int tile = blockIdx.x;          // 0..15
    const int g    = blockIdx.y;          // 0..7
    const int bb   = blockIdx.z;          // 0..3
    const int m0   = (tile >> 2) * 16;
    const int n0   = (tile & 3) * 16;
    const int t    = threadIdx.x;

    // load h0 slice (16 channels of this group) with zero-filled halo
    for (int idx = t; idx < 16 * 324; idx += 256) {
        int c  = idx / 324;
        int r2 = idx - c * 324;
        int mm = r2 / 18;
        int nn = r2 - mm * 18;
        int gm = m0 + mm - 1;
        int gn = n0 + nn - 1;
        float v = 0.f;
        if (gm >= 0 && gm < HLO && gn >= 0 && gn < WLO)
            v = g_h0[((size_t)(bb * COUT + g * GC_ + c)) * PLO + gm * WLO + gn];
        Hs[c * 336 + mm * 18 + nn] = v;
    }
    // load wgt tile: [25][16x16]
    for (int idx = t; idx < KK * 256; idx += 256) {
        int k  = idx >> 8;
        int pp = idx & 255;
        int ml = pp >> 4;
        int nl = pp & 15;
        Wg[idx] = g_wgt[((size_t)(bb * SPAN + g * KK + k)) * PLO + (m0 + ml) * WLO + (n0 + nl)];
    }
    __syncthreads();

    const int c  = t >> 4;    // 0..15 channel within group
    const int nl = t & 15;    // low col within tile
    const int xg = (n0 + nl) * 2;

    for (int ml = 0; ml < 16; ml++) {
        float wv[KK];
#pragma unroll
        for (int k = 0; k < KK; k++) wv[k] = Wg[k * 256 + ml * 16 + nl];
        float hv[9];
#pragma unroll
        for (int dr = 0; dr < 3; dr++)
#pragma unroll
            for (int dc = 0; dc < 3; dc++)
                hv[dr * 3 + dc] = Hs[c * 336 + (ml + dr) * 18 + (nl + dc)];

        float a00 = 0.f, a01 = 0.f, a10 = 0.f, a11 = 0.f;
#pragma unroll
        for (int kh = 0; kh < 5; kh++) {
#pragma unroll
            for (int kw = 0; kw < 5; kw++) {
                const float w = wv[kh * 5 + kw];
                const int r0 = ((kh - 2) >> 1) + 1;   // py=0 row
                const int r1 = ((kh - 1) >> 1) + 1;   // py=1 row
                const int c0 = ((kw - 2) >> 1) + 1;   // px=0 col
                const int c1 = ((kw - 1) >> 1) + 1;   // px=1 col
                a00 = fmaf(w, hv[r0 * 3 + c0], a00);
                a01 = fmaf(w, hv[r0 * 3 + c1], a01);
                a10 = fmaf(w, hv[r1 * 3 + c0], a10);
                a11 = fmaf(w, hv[r1 * 3 + c1], a11);
            }
        }
        const int yb = (m0 + ml) * 2;
        size_t ob = ((size_t)(bb * COUT + g * GC_ + c) * HF + yb) * WF + xg;
        *(float2*)&outp[ob]      = make_float2(a00, a01);
        *(float2*)&outp[ob + WF] = make_float2(a10, a11);
    }
}

// =====================================================================
// launcher
// =====================================================================
extern "C" void kernel_launch(void* const* d_in, const int* in_sizes, int n_in,
                              void* d_out, int out_size) {
    const float* x      = (const float*)d_in[0];
    const float* w1x1   = (const float*)d_in[1];
    const float* b1x1   = (const float*)d_in[2];
    const float* w_red  = (const float*)d_in[3];
    const float* b_red  = (const float*)d_in[4];
    const float* gamma  = (const float*)d_in[5];
    const float* beta   = (const float*)d_in[6];
    const float* mean   = (const float*)d_in[7];
    const float* var    = (const float*)d_in[8];
    const float* w_span = (const float*)d_in[9];
    const float* b_span = (const float*)d_in[10];
    float* out = (float*)d_out;

    k1_conv1x1 <<<dim3(PLO / 128, B_), 256>>>(x, w1x1, b1x1);
    k2_kernelgen<<<dim3(PLO / 128, B_), 256>>>(w_red, b_red, gamma, beta, mean, var,
                                               w_span, b_span);
    k3_involution<<<dim3(16, GROUPS, B_), 256>>>(out);
}